// round 3
// baseline (speedup 1.0000x reference)
#include <cuda_runtime.h>

#define T_   16384
#define NB   64
#define CIN  8
#define NH   32
#define NE   64
#define L_   512          // timesteps per segment
#define W_   64           // warm-up steps (v_in influence decays 2^-64 -> bit-exact)
#define NSEG 32           // T_/L_
#define XCOL (T_ + 4)     // transposed x columns incl. zero pads (idx = t+1)

// Device-global scratch (allocation-free contract). Globals are zero-init at
// module load; pad columns of g_xt are never written -> stay zero.
__device__ float    g_xt[(size_t)NB * XCOL * CIN];   // x transposed: [b][t+1][c]
__device__ unsigned g_mask[(size_t)NB * T_];         // layer-1 spikes: bit h of word (b,t)
__device__ unsigned g_m2[(size_t)NB * NE * (T_/32)]; // layer-2: [b*64+e][t/32], bit = t&31

// ---------------------------------------------------------------------------
// kT: transpose x[b][c][t] -> g_xt[b][t+1][c].  Coalesced both sides via smem.
// ---------------------------------------------------------------------------
__global__ void __launch_bounds__(256) kT(const float* __restrict__ x)
{
    __shared__ float tile[CIN][512 + 1];
    const int tid = threadIdx.x;
    const int b   = blockIdx.y;
    const int t0  = blockIdx.x * 512;

    const float* xb = x + (size_t)b * CIN * T_;
    for (int i = tid; i < CIN * 512; i += 256) {
        int c = i >> 9, t = i & 511;
        tile[c][t] = __ldg(xb + (size_t)c * T_ + t0 + t);
    }
    __syncthreads();
    float* op = g_xt + ((size_t)b * XCOL + t0 + 1) * CIN;
    for (int j = tid; j < 512 * CIN; j += 256)
        op[j] = tile[j & 7][j >> 3];
}

// ---------------------------------------------------------------------------
// kA: conv1(k=3,same) + BN1 + LIF1 -> g_mask.  One warp per (b, segment);
// lane = channel h.  No smem: uniform LDG.128 of g_xt columns, 4-phase
// register window.  LIF restructured bit-exactly (tau=2 -> *0.5 exact).
// ---------------------------------------------------------------------------
__global__ void __launch_bounds__(256) kA(
    const float* __restrict__ w1, const float* __restrict__ b1,
    const float* __restrict__ g1, const float* __restrict__ be1,
    const float* __restrict__ m1, const float* __restrict__ v1)
{
    const int lane = threadIdx.x & 31;
    const int gw   = blockIdx.x * 8 + (threadIdx.x >> 5);   // 0..2047
    const int seg  = gw & 31;
    const int b    = gw >> 5;
    const int t0   = seg * L_;

    float wk0[8], wk1[8], wk2[8];
#pragma unroll
    for (int c = 0; c < 8; c++) {
        wk0[c] = __ldg(&w1[(lane * CIN + c) * 3 + 0]);
        wk1[c] = __ldg(&w1[(lane * CIN + c) * 3 + 1]);
        wk2[c] = __ldg(&w1[(lane * CIN + c) * 3 + 2]);
    }
    const float bias = __ldg(&b1[lane]);
    const float sc = __fmul_rn(__ldg(&g1[lane]), __frsqrt_rn(__fadd_rn(__ldg(&v1[lane]), 1e-5f)));
    const float sh = __fsub_rn(__ldg(&be1[lane]), __fmul_rn(__ldg(&m1[lane]), sc));

    const int tstart = (seg == 0) ? 0 : (t0 - W_);
    // pt points at column x(t-1) for the time t about to be processed.
    const float* pt = g_xt + ((size_t)b * XCOL + tstart) * CIN;

    float vm = 0.0f;                 // pre-reset membrane of previous step
    bool  sp = false;                // spike at previous step
    unsigned mym = 0;

    float4 Aa = *(const float4*)(pt + 0),  Ab = *(const float4*)(pt + 4);
    float4 Ba = *(const float4*)(pt + 8),  Bb = *(const float4*)(pt + 12);
    float4 Ca = *(const float4*)(pt + 16), Cb = *(const float4*)(pt + 20);
    float4 Da, Db;

#define KA_STEP(Pa,Pb,Qa,Qb,Ra,Rb,La,Lb,OFF,DOEMIT,SI) { \
    La = *(const float4*)(pt + (OFF)); \
    Lb = *(const float4*)(pt + (OFF) + 4); \
    float acc = 0.0f; \
    acc=__fmaf_rn(wk0[0],Pa.x,acc); acc=__fmaf_rn(wk1[0],Qa.x,acc); acc=__fmaf_rn(wk2[0],Ra.x,acc); \
    acc=__fmaf_rn(wk0[1],Pa.y,acc); acc=__fmaf_rn(wk1[1],Qa.y,acc); acc=__fmaf_rn(wk2[1],Ra.y,acc); \
    acc=__fmaf_rn(wk0[2],Pa.z,acc); acc=__fmaf_rn(wk1[2],Qa.z,acc); acc=__fmaf_rn(wk2[2],Ra.z,acc); \
    acc=__fmaf_rn(wk0[3],Pa.w,acc); acc=__fmaf_rn(wk1[3],Qa.w,acc); acc=__fmaf_rn(wk2[3],Ra.w,acc); \
    acc=__fmaf_rn(wk0[4],Pb.x,acc); acc=__fmaf_rn(wk1[4],Qb.x,acc); acc=__fmaf_rn(wk2[4],Rb.x,acc); \
    acc=__fmaf_rn(wk0[5],Pb.y,acc); acc=__fmaf_rn(wk1[5],Qb.y,acc); acc=__fmaf_rn(wk2[5],Rb.y,acc); \
    acc=__fmaf_rn(wk0[6],Pb.z,acc); acc=__fmaf_rn(wk1[6],Qb.z,acc); acc=__fmaf_rn(wk2[6],Rb.z,acc); \
    acc=__fmaf_rn(wk0[7],Pb.w,acc); acc=__fmaf_rn(wk1[7],Qb.w,acc); acc=__fmaf_rn(wk2[7],Rb.w,acc); \
    float u   = __fadd_rn(__fmul_rn(__fadd_rn(acc, bias), sc), sh); \
    float dns = __fsub_rn(u, vm); \
    float dd  = sp ? u    : dns; \
    float vp  = sp ? 0.0f : vm; \
    vm = __fmaf_rn(dd, 0.5f, vp); \
    sp = (vm >= 1.0f); \
    if (DOEMIT) { unsigned bal = __ballot_sync(0xffffffffu, sp); \
                  if (lane == (SI)) mym = bal; } }

    if (seg != 0) {
#pragma unroll 1
        for (int s = 0; s < W_; s += 4) {
            KA_STEP(Aa,Ab,Ba,Bb,Ca,Cb,Da,Db, 24, 0, 0)
            KA_STEP(Ba,Bb,Ca,Cb,Da,Db,Aa,Ab, 32, 0, 0)
            KA_STEP(Ca,Cb,Da,Db,Aa,Ab,Ba,Bb, 40, 0, 0)
            KA_STEP(Da,Db,Aa,Ab,Ba,Bb,Ca,Cb, 48, 0, 0)
            pt += 32;
        }
    }
    unsigned* mp = g_mask + (size_t)b * T_ + t0;
#pragma unroll 1
    for (int g = 0; g < 16; g++) {
#pragma unroll 1
        for (int si = 0; si < 32; si += 4) {
            KA_STEP(Aa,Ab,Ba,Bb,Ca,Cb,Da,Db, 24, 1, si + 0)
            KA_STEP(Ba,Bb,Ca,Cb,Da,Db,Aa,Ab, 32, 1, si + 1)
            KA_STEP(Ca,Cb,Da,Db,Aa,Ab,Ba,Bb, 40, 1, si + 2)
            KA_STEP(Da,Db,Aa,Ab,Ba,Bb,Ca,Cb, 48, 1, si + 3)
            pt += 32;
        }
        mp[g * 32 + lane] = mym;
    }
#undef KA_STEP
}

// ---------------------------------------------------------------------------
// kB: sparse conv2 + BN2 + LIF2 -> per-channel bitmasks g_m2.  Block = 4
// warps = 4 consecutive segments of one batch, sharing weight tables in smem.
// Rolling 3-accumulator preserves the bit-exact summation order.
// Lane covers e0=2*lane and e0+1; spikes accumulate as shifted bits (no
// ballots): g_m2[b*64+e][t/32] bit (t&31).
// ---------------------------------------------------------------------------
#define MSZ (4 * L_ + W_ + 8)   // 2120

__global__ void __launch_bounds__(128) kB(
    const float* __restrict__ w2, const float* __restrict__ b2,
    const float* __restrict__ g2, const float* __restrict__ be2,
    const float* __restrict__ m2, const float* __restrict__ v2)
{
    __shared__ float4   ws4[NH * 32];   // [c][lane] = {k0e0,k0e1,k1e0,k1e1}
    __shared__ float2   ws2[NH * 32];   // [c][lane] = {k2e0,k2e1}
    __shared__ unsigned ms[MSZ];

    const int tid  = threadIdx.x;
    const int lane = tid & 31;
    const int w    = tid >> 5;
    const int b    = blockIdx.y;
    const int tblk = blockIdx.x * (4 * L_);

    for (int i = tid; i < NH * 32; i += 128) {
        int c = i >> 5, l = i & 31, e0 = l * 2;
        ws4[i] = make_float4(w2[(e0 * NH + c) * 3 + 0], w2[((e0 + 1) * NH + c) * 3 + 0],
                             w2[(e0 * NH + c) * 3 + 1], w2[((e0 + 1) * NH + c) * 3 + 1]);
        ws2[i] = make_float2(w2[(e0 * NH + c) * 3 + 2], w2[((e0 + 1) * NH + c) * 3 + 2]);
    }
    for (int j = tid; j < MSZ; j += 128) {
        int t = tblk - W_ - 1 + j;
        ms[j] = ((unsigned)t < (unsigned)T_) ? g_mask[(size_t)b * T_ + t] : 0u;
    }
    __syncthreads();

    const int seg  = blockIdx.x * 4 + w;
    const int t0   = seg * L_;
    const int base = w * L_;            // this warp's offset into ms
    const int e0   = lane * 2;

    const float sc0 = __fmul_rn(g2[e0],     __frsqrt_rn(__fadd_rn(v2[e0],     1e-5f)));
    const float sh0 = __fsub_rn(be2[e0],     __fmul_rn(m2[e0],     sc0));
    const float bb0 = b2[e0];
    const float sc1 = __fmul_rn(g2[e0 + 1], __frsqrt_rn(__fadd_rn(v2[e0 + 1], 1e-5f)));
    const float sh1 = __fsub_rn(be2[e0 + 1], __fmul_rn(m2[e0 + 1], sc1));
    const float bb1 = b2[e0 + 1];

    float aA0 = 0.f, aA1 = 0.f, aB0 = 0.f, aB1 = 0.f, aC0 = 0.f, aC1 = 0.f;
    float vm0 = 0.f, vm1 = 0.f;
    bool  sp0 = false, sp1 = false;
    unsigned me = 0, mo = 0;

    const int s0 = (seg == 0) ? W_ : 0;

    // Prime: word(s0) contributes tap0 to y(t(s0)); word(s0+1) tap1->A, tap0->B.
    { unsigned r = ms[base + s0];
      while (r) { int c = __ffs(r) - 1; r &= r - 1;
          float4 q = ws4[(c << 5) + lane];
          aA0 = __fadd_rn(aA0, q.x); aA1 = __fadd_rn(aA1, q.y); } }
    { unsigned r = ms[base + s0 + 1];
      while (r) { int c = __ffs(r) - 1; r &= r - 1;
          float4 q = ws4[(c << 5) + lane];
          aA0 = __fadd_rn(aA0, q.z); aA1 = __fadd_rn(aA1, q.w);
          aB0 = __fadd_rn(aB0, q.x); aB1 = __fadd_rn(aB1, q.y); } }

#define KB_STEP(JW, DOEMIT, SI) { \
    unsigned r = ms[JW]; \
    while (r) { int c = __ffs(r) - 1; r &= r - 1; \
        float4 q = ws4[(c << 5) + lane]; \
        float2 p = ws2[(c << 5) + lane]; \
        aA0 = __fadd_rn(aA0, p.x); aA1 = __fadd_rn(aA1, p.y); \
        aB0 = __fadd_rn(aB0, q.z); aB1 = __fadd_rn(aB1, q.w); \
        aC0 = __fadd_rn(aC0, q.x); aC1 = __fadd_rn(aC1, q.y); } \
    float u0 = __fadd_rn(__fmul_rn(__fadd_rn(aA0, bb0), sc0), sh0); \
    float u1 = __fadd_rn(__fmul_rn(__fadd_rn(aA1, bb1), sc1), sh1); \
    float d0 = __fsub_rn(u0, vm0); float dd0 = sp0 ? u0 : d0; float vp0 = sp0 ? 0.0f : vm0; \
    vm0 = __fmaf_rn(dd0, 0.5f, vp0); sp0 = (vm0 >= 1.0f); \
    float d1 = __fsub_rn(u1, vm1); float dd1 = sp1 ? u1 : d1; float vp1 = sp1 ? 0.0f : vm1; \
    vm1 = __fmaf_rn(dd1, 0.5f, vp1); sp1 = (vm1 >= 1.0f); \
    aA0 = aB0; aA1 = aB1; aB0 = aC0; aB1 = aC1; aC0 = 0.0f; aC1 = 0.0f; \
    if (DOEMIT) { me |= ((unsigned)sp0) << (SI); \
                  mo |= ((unsigned)sp1) << (SI); } }

    if (seg != 0) {
#pragma unroll 1
        for (int s = 0; s < W_; s++) KB_STEP(base + s + 2, 0, 0)
    }
    unsigned* mpE = g_m2 + ((size_t)b * NE + e0)     * (T_/32) + seg * 16;
    unsigned* mpO = g_m2 + ((size_t)b * NE + e0 + 1) * (T_/32) + seg * 16;
#pragma unroll 1
    for (int g = 0; g < 16; g++) {
        const int jb = base + W_ + g * 32 + 2;
#pragma unroll 1
        for (int si = 0; si < 32; si++) KB_STEP(jb + si, 1, si)
        mpE[g] = me;  me = 0;
        mpO[g] = mo;  mo = 0;
    }
#undef KB_STEP
}

// ---------------------------------------------------------------------------
// kC: expand per-channel bitmasks -> out[B,E,T] float 0/1.  Warp = one
// (b,e) row; fully coalesced reads and STG.128 writes.
// ---------------------------------------------------------------------------
__global__ void __launch_bounds__(256) kC(float* __restrict__ out)
{
    const int lane = threadIdx.x & 31;
    const int row  = blockIdx.x * 8 + (threadIdx.x >> 5);   // 0..4095 = b*64+e
    const unsigned* mp = g_m2 + (size_t)row * (T_/32);
    float* op = out + (size_t)row * T_;
    const int wsel = lane >> 3;
    const int bb   = (lane & 7) * 4;

#pragma unroll 4
    for (int i = 0; i < 128; i++) {
        unsigned m = __ldg(&mp[i * 4 + wsel]);
        float4 v;
        v.x = ((m >> (bb + 0)) & 1u) ? 1.0f : 0.0f;
        v.y = ((m >> (bb + 1)) & 1u) ? 1.0f : 0.0f;
        v.z = ((m >> (bb + 2)) & 1u) ? 1.0f : 0.0f;
        v.w = ((m >> (bb + 3)) & 1u) ? 1.0f : 0.0f;
        *(float4*)&op[i * 128 + lane * 4] = v;
    }
}

// ---------------------------------------------------------------------------
extern "C" void kernel_launch(void* const* d_in, const int* in_sizes, int n_in,
                              void* d_out, int out_size)
{
    const float* x   = (const float*)d_in[0];
    const float* w1  = (const float*)d_in[1];
    const float* b1  = (const float*)d_in[2];
    const float* g1  = (const float*)d_in[3];
    const float* be1 = (const float*)d_in[4];
    const float* m1  = (const float*)d_in[5];
    const float* v1  = (const float*)d_in[6];
    const float* w2  = (const float*)d_in[7];
    const float* b2  = (const float*)d_in[8];
    const float* g2  = (const float*)d_in[9];
    const float* be2 = (const float*)d_in[10];
    const float* m2  = (const float*)d_in[11];
    const float* v2  = (const float*)d_in[12];
    float* out = (float*)d_out;

    kT<<<dim3(32, 64), 256>>>(x);
    kA<<<256, 256>>>(w1, b1, g1, be1, m1, v1);
    kB<<<dim3(NSEG / 4, NB), 128>>>(w2, b2, g2, be2, m2, v2);
    kC<<<512, 256>>>(out);
}

// round 4
// speedup vs baseline: 1.4427x; 1.4427x over previous
#include <cuda_runtime.h>

#define T_    16384
#define NB    64
#define CIN   8
#define NH    32
#define NE    64
#define LA_   512         // kA segment length
#define W_    64          // warm-up steps (state influence decays 2^-64 -> exact)
#define XS2   292         // kA staged cols per phase (288 steps + window + prefetch pad)
#define LB_   256         // kB segment length
#define MSZ   (2048 + W_ + 10)   // kB staged mask words per block

// Layer-1 spike bitmasks: word (b,t), bit = channel h. (allocation-free contract)
__device__ unsigned g_mask[(size_t)NB * T_];

// ---------------------------------------------------------------------------
// kA: conv1(k=3,same) + BN1 + LIF1 -> g_mask.  One warp per (b, segment);
// lane = channel h.  x window staged in smem in TWO phases (9.3KB) so all
// 2048 warps stay resident.  4-phase register window; LIF restructured
// bit-exactly (tau=2 -> *0.5 exact).
// ---------------------------------------------------------------------------
__global__ void __launch_bounds__(32) kA(
    const float* __restrict__ x,  const float* __restrict__ w1,
    const float* __restrict__ b1, const float* __restrict__ g1,
    const float* __restrict__ be1,const float* __restrict__ m1,
    const float* __restrict__ v1)
{
    __shared__ float xs[XS2 * CIN];
    const int lane = threadIdx.x;
    const int seg  = blockIdx.x;
    const int b    = blockIdx.y;
    const int t0   = seg * LA_;

    float wk0[8], wk1[8], wk2[8];
#pragma unroll
    for (int c = 0; c < 8; c++) {
        wk0[c] = __ldg(&w1[(lane * CIN + c) * 3 + 0]);
        wk1[c] = __ldg(&w1[(lane * CIN + c) * 3 + 1]);
        wk2[c] = __ldg(&w1[(lane * CIN + c) * 3 + 2]);
    }
    const float bias = __ldg(&b1[lane]);
    const float sc = __fmul_rn(__ldg(&g1[lane]), __frsqrt_rn(__fadd_rn(__ldg(&v1[lane]), 1e-5f)));
    const float sh = __fsub_rn(__ldg(&be1[lane]), __fmul_rn(__ldg(&m1[lane]), sc));

    const float* xb = x + (size_t)b * CIN * T_;
    const int tb = (seg == 0) ? 0 : (t0 - W_);
    const int S  = (seg == 0) ? LA_ : (LA_ + W_);
    const int warmChunks = (seg == 0) ? 0 : 2;

    float vm = 0.0f;                 // pre-reset membrane of previous step
    bool  sp = false;                // spike at previous step
    unsigned mym = 0;
    unsigned* mp = g_mask + (size_t)b * T_ + t0;
    int grp = 0;

#define KA_STEP(Pa,Pb,Qa,Qb,Ra,Rb,La,Lb,OFF,DOEMIT,SI) { \
    La = *(const float4*)(pt + (OFF)); \
    Lb = *(const float4*)(pt + (OFF) + 4); \
    float acc = 0.0f; \
    acc=__fmaf_rn(wk0[0],Pa.x,acc); acc=__fmaf_rn(wk1[0],Qa.x,acc); acc=__fmaf_rn(wk2[0],Ra.x,acc); \
    acc=__fmaf_rn(wk0[1],Pa.y,acc); acc=__fmaf_rn(wk1[1],Qa.y,acc); acc=__fmaf_rn(wk2[1],Ra.y,acc); \
    acc=__fmaf_rn(wk0[2],Pa.z,acc); acc=__fmaf_rn(wk1[2],Qa.z,acc); acc=__fmaf_rn(wk2[2],Ra.z,acc); \
    acc=__fmaf_rn(wk0[3],Pa.w,acc); acc=__fmaf_rn(wk1[3],Qa.w,acc); acc=__fmaf_rn(wk2[3],Ra.w,acc); \
    acc=__fmaf_rn(wk0[4],Pb.x,acc); acc=__fmaf_rn(wk1[4],Qb.x,acc); acc=__fmaf_rn(wk2[4],Rb.x,acc); \
    acc=__fmaf_rn(wk0[5],Pb.y,acc); acc=__fmaf_rn(wk1[5],Qb.y,acc); acc=__fmaf_rn(wk2[5],Rb.y,acc); \
    acc=__fmaf_rn(wk0[6],Pb.z,acc); acc=__fmaf_rn(wk1[6],Qb.z,acc); acc=__fmaf_rn(wk2[6],Rb.z,acc); \
    acc=__fmaf_rn(wk0[7],Pb.w,acc); acc=__fmaf_rn(wk1[7],Qb.w,acc); acc=__fmaf_rn(wk2[7],Rb.w,acc); \
    float u   = __fadd_rn(__fmul_rn(__fadd_rn(acc, bias), sc), sh); \
    float dns = __fsub_rn(u, vm); \
    float dd  = sp ? u    : dns; \
    float vp  = sp ? 0.0f : vm; \
    vm = __fmaf_rn(dd, 0.5f, vp); \
    sp = (vm >= 1.0f); \
    if (DOEMIT) { unsigned bal = __ballot_sync(0xffffffffu, sp); \
                  if (lane == (SI)) mym = bal; } }

#pragma unroll 1
    for (int p = 0; p < 2; p++) {
        const int sbeg  = p * 288;
        const int send  = (S < sbeg + 288) ? S : (sbeg + 288);
        const int ncols = send - sbeg + 2;
        const int tp    = tb + sbeg;
        __syncwarp();
        // Stage cols j -> time tp-1+j, transposed (xs[j*8+c]); STS.128 pairs.
#pragma unroll 1
        for (int j = lane; j < ncols; j += 32) {
            int t = tp - 1 + j;
            bool ok = ((unsigned)t < (unsigned)T_);
            float v0 = ok ? __ldg(xb + 0 * T_ + t) : 0.0f;
            float v1_ = ok ? __ldg(xb + 1 * T_ + t) : 0.0f;
            float v2_ = ok ? __ldg(xb + 2 * T_ + t) : 0.0f;
            float v3_ = ok ? __ldg(xb + 3 * T_ + t) : 0.0f;
            float v4_ = ok ? __ldg(xb + 4 * T_ + t) : 0.0f;
            float v5_ = ok ? __ldg(xb + 5 * T_ + t) : 0.0f;
            float v6_ = ok ? __ldg(xb + 6 * T_ + t) : 0.0f;
            float v7_ = ok ? __ldg(xb + 7 * T_ + t) : 0.0f;
            *(float4*)&xs[j * 8]     = make_float4(v0, v1_, v2_, v3_);
            *(float4*)&xs[j * 8 + 4] = make_float4(v4_, v5_, v6_, v7_);
        }
        __syncwarp();

        const float* pt = xs;
        float4 Aa = *(const float4*)(pt + 0),  Ab = *(const float4*)(pt + 4);
        float4 Ba = *(const float4*)(pt + 8),  Bb = *(const float4*)(pt + 12);
        float4 Ca = *(const float4*)(pt + 16), Cb = *(const float4*)(pt + 20);
        float4 Da, Db;

        const int ch0 = sbeg >> 5, ch1 = send >> 5;
#pragma unroll 1
        for (int ch = ch0; ch < ch1; ch++) {
            if (ch < warmChunks) {
#pragma unroll 1
                for (int si = 0; si < 32; si += 4) {
                    KA_STEP(Aa,Ab,Ba,Bb,Ca,Cb,Da,Db, 24, 0, 0)
                    KA_STEP(Ba,Bb,Ca,Cb,Da,Db,Aa,Ab, 32, 0, 0)
                    KA_STEP(Ca,Cb,Da,Db,Aa,Ab,Ba,Bb, 40, 0, 0)
                    KA_STEP(Da,Db,Aa,Ab,Ba,Bb,Ca,Cb, 48, 0, 0)
                    pt += 32;
                }
            } else {
#pragma unroll 1
                for (int si = 0; si < 32; si += 4) {
                    KA_STEP(Aa,Ab,Ba,Bb,Ca,Cb,Da,Db, 24, 1, si + 0)
                    KA_STEP(Ba,Bb,Ca,Cb,Da,Db,Aa,Ab, 32, 1, si + 1)
                    KA_STEP(Ca,Cb,Da,Db,Aa,Ab,Ba,Bb, 40, 1, si + 2)
                    KA_STEP(Da,Db,Aa,Ab,Ba,Bb,Ca,Cb, 48, 1, si + 3)
                    pt += 32;
                }
                mp[grp * 32 + lane] = mym;
                grp++;
            }
        }
    }
#undef KA_STEP
}

// ---------------------------------------------------------------------------
// kB: sparse conv2 + BN2 + LIF2 + output expansion -> out[B,E,T].
// Block = 8 warps = 8 consecutive 256-step segments of one batch (4096 warps
// total -> ~28 resident warps/SM, 4x R3's latency hiding).  Rolling
// 3-accumulator preserves the bit-exact summation order.  Lane covers
// e0=2*lane, e0+1; spikes accumulate as shifted bits; every 32 steps the
// warp's 64 channel-words are staged in smem and expanded to coalesced
// float4 stores (no separate expansion kernel, no mask round-trip).
// ---------------------------------------------------------------------------
__global__ void __launch_bounds__(256) kB(
    const float* __restrict__ w2, const float* __restrict__ b2,
    const float* __restrict__ g2, const float* __restrict__ be2,
    const float* __restrict__ m2, const float* __restrict__ v2,
    float* __restrict__ out)
{
    __shared__ float4   ws4[NH * 32];   // [c][lane] = {k0e0,k0e1,k1e0,k1e1}
    __shared__ float2   ws2[NH * 32];   // [c][lane] = {k2e0,k2e1}
    __shared__ unsigned ms[MSZ];
    __shared__ unsigned es[8][NE];      // per-warp expansion staging

    const int tid  = threadIdx.x;
    const int lane = tid & 31;
    const int w    = tid >> 5;
    const int b    = blockIdx.y;
    const int tblk = blockIdx.x * (8 * LB_);

    for (int i = tid; i < NH * 32; i += 256) {
        int c = i >> 5, l = i & 31, ee = l * 2;
        ws4[i] = make_float4(w2[(ee * NH + c) * 3 + 0], w2[((ee + 1) * NH + c) * 3 + 0],
                             w2[(ee * NH + c) * 3 + 1], w2[((ee + 1) * NH + c) * 3 + 1]);
        ws2[i] = make_float2(w2[(ee * NH + c) * 3 + 2], w2[((ee + 1) * NH + c) * 3 + 2]);
    }
    for (int j = tid; j < MSZ; j += 256) {
        int t = tblk - W_ - 1 + j;
        ms[j] = ((unsigned)t < (unsigned)T_) ? g_mask[(size_t)b * T_ + t] : 0u;
    }
    __syncthreads();

    const int segg = blockIdx.x * 8 + w;     // global 256-step segment id
    const int t0   = tblk + w * LB_;
    const int base = w * LB_;                // ms[base+j] <-> t = t0 - W_ - 1 + j
    const int e0   = lane * 2;

    const float sc0 = __fmul_rn(g2[e0],     __frsqrt_rn(__fadd_rn(v2[e0],     1e-5f)));
    const float sh0 = __fsub_rn(be2[e0],     __fmul_rn(m2[e0],     sc0));
    const float bb0 = b2[e0];
    const float sc1 = __fmul_rn(g2[e0 + 1], __frsqrt_rn(__fadd_rn(v2[e0 + 1], 1e-5f)));
    const float sh1 = __fsub_rn(be2[e0 + 1], __fmul_rn(m2[e0 + 1], sc1));
    const float bb1 = b2[e0 + 1];

    float aA0 = 0.f, aA1 = 0.f, aB0 = 0.f, aB1 = 0.f, aC0 = 0.f, aC1 = 0.f;
    float vm0 = 0.f, vm1 = 0.f;
    bool  sp0 = false, sp1 = false;
    unsigned me = 0, mo = 0;

    const int s0 = (segg == 0) ? W_ : 0;

    // Prime: word(tstart-1) tap0 -> A; word(tstart) tap1 -> A, tap0 -> B.
    { unsigned r = ms[base + s0];
      while (r) { int c = __ffs(r) - 1; r &= r - 1;
          float4 q = ws4[(c << 5) + lane];
          aA0 = __fadd_rn(aA0, q.x); aA1 = __fadd_rn(aA1, q.y); } }
    { unsigned r = ms[base + s0 + 1];
      while (r) { int c = __ffs(r) - 1; r &= r - 1;
          float4 q = ws4[(c << 5) + lane];
          aA0 = __fadd_rn(aA0, q.z); aA1 = __fadd_rn(aA1, q.w);
          aB0 = __fadd_rn(aB0, q.x); aB1 = __fadd_rn(aB1, q.y); } }

#define KB_STEP(JW, DOEMIT, SI) { \
    unsigned r = ms[JW]; \
    while (r) { int c = __ffs(r) - 1; r &= r - 1; \
        float4 q = ws4[(c << 5) + lane]; \
        float2 p = ws2[(c << 5) + lane]; \
        aA0 = __fadd_rn(aA0, p.x); aA1 = __fadd_rn(aA1, p.y); \
        aB0 = __fadd_rn(aB0, q.z); aB1 = __fadd_rn(aB1, q.w); \
        aC0 = __fadd_rn(aC0, q.x); aC1 = __fadd_rn(aC1, q.y); } \
    float u0 = __fadd_rn(__fmul_rn(__fadd_rn(aA0, bb0), sc0), sh0); \
    float u1 = __fadd_rn(__fmul_rn(__fadd_rn(aA1, bb1), sc1), sh1); \
    float d0 = __fsub_rn(u0, vm0); float dd0 = sp0 ? u0 : d0; float vp0 = sp0 ? 0.0f : vm0; \
    vm0 = __fmaf_rn(dd0, 0.5f, vp0); sp0 = (vm0 >= 1.0f); \
    float d1 = __fsub_rn(u1, vm1); float dd1 = sp1 ? u1 : d1; float vp1 = sp1 ? 0.0f : vm1; \
    vm1 = __fmaf_rn(dd1, 0.5f, vp1); sp1 = (vm1 >= 1.0f); \
    aA0 = aB0; aA1 = aB1; aB0 = aC0; aB1 = aC1; aC0 = 0.0f; aC1 = 0.0f; \
    if (DOEMIT) { me |= ((unsigned)sp0) << (SI); \
                  mo |= ((unsigned)sp1) << (SI); } }

    if (segg != 0) {
#pragma unroll 1
        for (int s = 0; s < W_; s++) KB_STEP(base + s + 2, 0, 0)
    }

    float* ob = out + (size_t)b * NE * T_ + t0;
#pragma unroll 1
    for (int g = 0; g < 8; g++) {
        const int jb = base + W_ + g * 32 + 2;
#pragma unroll 1
        for (int si = 0; si < 32; si++) KB_STEP(jb + si, 1, si)

        *(uint2*)&es[w][e0] = make_uint2(me, mo);
        __syncwarp();
#pragma unroll
        for (int i = 0; i < 16; i++) {
            int idx = i * 32 + lane;          // 0..511
            int e   = idx >> 3;               // 0..63
            int q4  = (idx & 7) * 4;          // 0,4,..,28
            unsigned m = es[w][e];
            float4 v;
            v.x = ((m >> (q4 + 0)) & 1u) ? 1.0f : 0.0f;
            v.y = ((m >> (q4 + 1)) & 1u) ? 1.0f : 0.0f;
            v.z = ((m >> (q4 + 2)) & 1u) ? 1.0f : 0.0f;
            v.w = ((m >> (q4 + 3)) & 1u) ? 1.0f : 0.0f;
            *(float4*)&ob[(size_t)e * T_ + g * 32 + q4] = v;
        }
        __syncwarp();
        me = 0; mo = 0;
    }
#undef KB_STEP
}

// ---------------------------------------------------------------------------
extern "C" void kernel_launch(void* const* d_in, const int* in_sizes, int n_in,
                              void* d_out, int out_size)
{
    const float* x   = (const float*)d_in[0];
    const float* w1  = (const float*)d_in[1];
    const float* b1  = (const float*)d_in[2];
    const float* g1  = (const float*)d_in[3];
    const float* be1 = (const float*)d_in[4];
    const float* m1  = (const float*)d_in[5];
    const float* v1  = (const float*)d_in[6];
    const float* w2  = (const float*)d_in[7];
    const float* b2  = (const float*)d_in[8];
    const float* g2  = (const float*)d_in[9];
    const float* be2 = (const float*)d_in[10];
    const float* m2  = (const float*)d_in[11];
    const float* v2  = (const float*)d_in[12];
    float* out = (float*)d_out;

    kA<<<dim3(32, 64), 32>>>(x, w1, b1, g1, be1, m1, v1);
    kB<<<dim3(8, 64), 256>>>(w2, b2, g2, be2, m2, v2, out);
}